// round 1
// baseline (speedup 1.0000x reference)
#include <cuda_runtime.h>
#include <math.h>

#define T_TOKENS 8192
#define H_DIM    2048
#define I_DIM    1408
#define N_EXP    8
#define MAXTOK   8192

// ---- scratch (static device globals; no allocation) ----
__device__ float g_xn[T_TOKENS * H_DIM];          // normalized activations  (67 MB)
__device__ float g_h [2 * T_TOKENS * I_DIM];      // GLU intermediate        (92 MB)
__device__ int   g_cnt[N_EXP];
__device__ int   g_off[N_EXP];
__device__ int   g_tok[N_EXP * MAXTOK];
__device__ float g_wt [N_EXP * MAXTOK];

// ---------------------------------------------------------------------------
__global__ void reset_kernel() {
    if (threadIdx.x < N_EXP) g_cnt[threadIdx.x] = 0;
}

// ---------------------------------------------------------------------------
// Per-token: RMSNorm, router logits, softmax, top-2, expert assignment.
__global__ __launch_bounds__(256) void router_kernel(
    const float* __restrict__ hs,
    const float* __restrict__ rmsw,
    const float* __restrict__ rw,
    float* __restrict__ out,
    float* __restrict__ out_logits)
{
    const int t   = blockIdx.x;
    const int tid = threadIdx.x;
    const float* x  = hs + (size_t)t * H_DIM;
    float*       xn = g_xn + (size_t)t * H_DIM;
    float*       o  = out  + (size_t)t * H_DIM;

    // zero the output row (d_out is poisoned)
    for (int i = tid; i < H_DIM; i += 256) o[i] = 0.f;

    // sum of squares
    float ss = 0.f;
    for (int i = tid; i < H_DIM; i += 256) { float v = x[i]; ss += v * v; }
    __shared__ float red[256];
    red[tid] = ss; __syncthreads();
    for (int s = 128; s > 0; s >>= 1) {
        if (tid < s) red[tid] += red[tid + s];
        __syncthreads();
    }
    __shared__ float s_scale;
    if (tid == 0) s_scale = rsqrtf(red[0] / (float)H_DIM + 1e-6f);
    __syncthreads();
    const float scale = s_scale;

    // normalized activations + 8 router dot products
    float acc[N_EXP];
#pragma unroll
    for (int e = 0; e < N_EXP; e++) acc[e] = 0.f;
    for (int i = tid; i < H_DIM; i += 256) {
        float v = x[i] * scale * rmsw[i];
        xn[i] = v;
#pragma unroll
        for (int e = 0; e < N_EXP; e++) acc[e] += v * rw[e * H_DIM + i];
    }

    __shared__ float slog[N_EXP];
    for (int e = 0; e < N_EXP; e++) {
        __syncthreads();
        red[tid] = acc[e]; __syncthreads();
        for (int s = 128; s > 0; s >>= 1) {
            if (tid < s) red[tid] += red[tid + s];
            __syncthreads();
        }
        if (tid == 0) slog[e] = red[0];
    }
    __syncthreads();

    if (tid == 0) {
        float l[N_EXP], m = -1e30f;
#pragma unroll
        for (int e = 0; e < N_EXP; e++) {
            l[e] = slog[e];
            out_logits[(size_t)t * N_EXP + e] = l[e];
            m = fmaxf(m, l[e]);
        }
        float p[N_EXP], s = 0.f;
#pragma unroll
        for (int e = 0; e < N_EXP; e++) { p[e] = expf(l[e] - m); s += p[e]; }
#pragma unroll
        for (int e = 0; e < N_EXP; e++) p[e] /= s;

        int a = 0;
#pragma unroll
        for (int e = 1; e < N_EXP; e++) if (p[e] > p[a]) a = e;
        int b = (a == 0) ? 1 : 0;
#pragma unroll
        for (int e = 0; e < N_EXP; e++) if (e != a && p[e] > p[b]) b = e;

        float wsum = p[a] + p[b] + 1e-20f;
        float wa = p[a] / wsum;
        float wb = p[b] / wsum;

        int pa = atomicAdd(&g_cnt[a], 1);
        g_tok[a * MAXTOK + pa] = t;  g_wt[a * MAXTOK + pa] = wa;
        int pb = atomicAdd(&g_cnt[b], 1);
        g_tok[b * MAXTOK + pb] = t;  g_wt[b * MAXTOK + pb] = wb;
    }
}

// ---------------------------------------------------------------------------
__global__ void offsets_kernel() {
    int run = 0;
    for (int e = 0; e < N_EXP; e++) { g_off[e] = run; run += g_cnt[e]; }
}

// ---------------------------------------------------------------------------
// GEMM1: for expert e, G = Xe @ Wg^T, U = Xe @ Wu^T, h = silu(G) * U.
// Tile: 128(M) x 64(N) x 16(K), 256 threads, per-thread 8x4 x2 accumulators.
#define TM 128
#define TN 64
#define TK 16

__global__ __launch_bounds__(256) void gemm1_kernel(
    const float* __restrict__ wg, const float* __restrict__ wu)
{
    const int e  = blockIdx.z;
    const int mt = blockIdx.y;
    const int nt = blockIdx.x;
    const int cnt = g_cnt[e];
    if (mt * TM >= cnt) return;
    const int tid = threadIdx.x;

    __shared__ float As[TK][TM + 4];
    __shared__ float Bg[TK][TN + 4];
    __shared__ float Bu[TK][TN + 4];
    __shared__ int   stok[TM];

    if (tid < TM) {
        int row = mt * TM + tid;
        stok[tid] = (row < cnt) ? g_tok[e * MAXTOK + row] : -1;
    }
    __syncthreads();

    const float* wge = wg + (size_t)e * I_DIM * H_DIM + (size_t)(nt * TN) * H_DIM;
    const float* wue = wu + (size_t)e * I_DIM * H_DIM + (size_t)(nt * TN) * H_DIM;

    float accg[8][4], accu[8][4];
#pragma unroll
    for (int i = 0; i < 8; i++)
#pragma unroll
        for (int j = 0; j < 4; j++) { accg[i][j] = 0.f; accu[i][j] = 0.f; }

    const int tm = tid >> 4;   // 0..15 -> rows tm*8..tm*8+7
    const int tn = tid & 15;   // 0..15 -> cols tn*4..tn*4+3

    for (int kk = 0; kk < H_DIM; kk += TK) {
        // A: 128 x 16 (gathered rows)
#pragma unroll
        for (int r = 0; r < 8; r++) {
            int idx = tid + r * 256;
            int m = idx >> 4, k = idx & 15;
            int tok = stok[m];
            As[k][m] = (tok >= 0) ? g_xn[(size_t)tok * H_DIM + kk + k] : 0.f;
        }
        // B tiles: 64 x 16 each
#pragma unroll
        for (int r = 0; r < 4; r++) {
            int idx = tid + r * 256;
            int n = idx >> 4, k = idx & 15;
            Bg[k][n] = wge[(size_t)n * H_DIM + kk + k];
            Bu[k][n] = wue[(size_t)n * H_DIM + kk + k];
        }
        __syncthreads();

#pragma unroll
        for (int k = 0; k < TK; k++) {
            float a[8], bg[4], bu[4];
#pragma unroll
            for (int i = 0; i < 8; i++) a[i] = As[k][tm * 8 + i];
#pragma unroll
            for (int j = 0; j < 4; j++) { bg[j] = Bg[k][tn * 4 + j]; bu[j] = Bu[k][tn * 4 + j]; }
#pragma unroll
            for (int i = 0; i < 8; i++)
#pragma unroll
                for (int j = 0; j < 4; j++) {
                    accg[i][j] += a[i] * bg[j];
                    accu[i][j] += a[i] * bu[j];
                }
        }
        __syncthreads();
    }

    const int off = g_off[e];
#pragma unroll
    for (int i = 0; i < 8; i++) {
        int m = mt * TM + tm * 8 + i;
        if (m < cnt) {
            float* hr = g_h + (size_t)(off + m) * I_DIM + nt * TN + tn * 4;
#pragma unroll
            for (int j = 0; j < 4; j++) {
                float g = accg[i][j], u = accu[i][j];
                hr[j] = (g / (1.f + expf(-g))) * u;   // silu(g) * u
            }
        }
    }
}

// ---------------------------------------------------------------------------
// GEMM2: Y = He @ Wd^T, scaled by combine weight, atomic scatter-add into out.
__global__ __launch_bounds__(256) void gemm2_kernel(
    const float* __restrict__ wd, float* __restrict__ out)
{
    const int e  = blockIdx.z;
    const int mt = blockIdx.y;
    const int nt = blockIdx.x;
    const int cnt = g_cnt[e];
    if (mt * TM >= cnt) return;
    const int tid = threadIdx.x;
    const int off = g_off[e];

    __shared__ float As[TK][TM + 4];
    __shared__ float Bs[TK][TN + 4];
    __shared__ int   stok[TM];
    __shared__ float swt[TM];

    if (tid < TM) {
        int row = mt * TM + tid;
        if (row < cnt) {
            stok[tid] = g_tok[e * MAXTOK + row];
            swt[tid]  = g_wt [e * MAXTOK + row];
        } else {
            stok[tid] = -1; swt[tid] = 0.f;
        }
    }
    __syncthreads();

    const float* wde = wd + (size_t)e * H_DIM * I_DIM + (size_t)(nt * TN) * I_DIM;

    float acc[8][4];
#pragma unroll
    for (int i = 0; i < 8; i++)
#pragma unroll
        for (int j = 0; j < 4; j++) acc[i][j] = 0.f;

    const int tm = tid >> 4;
    const int tn = tid & 15;

    for (int kk = 0; kk < I_DIM; kk += TK) {
#pragma unroll
        for (int r = 0; r < 8; r++) {
            int idx = tid + r * 256;
            int m = idx >> 4, k = idx & 15;
            int row = mt * TM + m;
            As[k][m] = (row < cnt) ? g_h[(size_t)(off + row) * I_DIM + kk + k] : 0.f;
        }
#pragma unroll
        for (int r = 0; r < 4; r++) {
            int idx = tid + r * 256;
            int n = idx >> 4, k = idx & 15;
            Bs[k][n] = wde[(size_t)n * I_DIM + kk + k];
        }
        __syncthreads();

#pragma unroll
        for (int k = 0; k < TK; k++) {
            float a[8], b[4];
#pragma unroll
            for (int i = 0; i < 8; i++) a[i] = As[k][tm * 8 + i];
#pragma unroll
            for (int j = 0; j < 4; j++) b[j] = Bs[k][tn * 4 + j];
#pragma unroll
            for (int i = 0; i < 8; i++)
#pragma unroll
                for (int j = 0; j < 4; j++) acc[i][j] += a[i] * b[j];
        }
        __syncthreads();
    }

#pragma unroll
    for (int i = 0; i < 8; i++) {
        int mloc = tm * 8 + i;
        int m = mt * TM + mloc;
        if (m < cnt) {
            int tok = stok[mloc];
            float w = swt[mloc];
            float* orow = out + (size_t)tok * H_DIM + nt * TN + tn * 4;
#pragma unroll
            for (int j = 0; j < 4; j++) atomicAdd(&orow[j], w * acc[i][j]);
        }
    }
}

// ---------------------------------------------------------------------------
extern "C" void kernel_launch(void* const* d_in, const int* in_sizes, int n_in,
                              void* d_out, int out_size)
{
    const float* hs   = (const float*)d_in[0];  // [4,2048,2048]
    const float* rmsw = (const float*)d_in[1];  // [2048]
    const float* rw   = (const float*)d_in[2];  // [8,2048]
    const float* wg   = (const float*)d_in[3];  // [8,1408,2048]
    const float* wu   = (const float*)d_in[4];  // [8,1408,2048]
    const float* wd   = (const float*)d_in[5];  // [8,2048,1408]

    float* out        = (float*)d_out;                         // [T, H]
    float* out_logits = (float*)d_out + (size_t)T_TOKENS * H_DIM;  // [T, 8]

    reset_kernel<<<1, 32>>>();
    router_kernel<<<T_TOKENS, 256>>>(hs, rmsw, rw, out, out_logits);
    offsets_kernel<<<1, 1>>>();

    dim3 g1(I_DIM / TN, (T_TOKENS + TM - 1) / TM, N_EXP);  // 22 x 64 x 8
    gemm1_kernel<<<g1, 256>>>(wg, wu);

    dim3 g2(H_DIM / TN, (T_TOKENS + TM - 1) / TM, N_EXP);  // 32 x 64 x 8
    gemm2_kernel<<<g2, 256>>>(wd, out);
}

// round 3
// speedup vs baseline: 4.7605x; 4.7605x over previous
#include <cuda_runtime.h>
#include <cuda_bf16.h>
#include <math.h>
#include <stdint.h>

#define T_TOKENS 8192
#define H_DIM    2048
#define I_DIM    1408
#define N_EXP    8
#define MAXTOK   8192
#define TOTROWS  (2*T_TOKENS)

// ---------------- scratch (static device globals) ----------------
__device__ __nv_bfloat16 g_xn_hi[(size_t)T_TOKENS*H_DIM];
__device__ __nv_bfloat16 g_xn_lo[(size_t)T_TOKENS*H_DIM];
__device__ __nv_bfloat16 g_h_hi[(size_t)(TOTROWS+128)*I_DIM];
__device__ __nv_bfloat16 g_h_lo[(size_t)(TOTROWS+128)*I_DIM];
__device__ float g_y[(size_t)TOTROWS*H_DIM];
__device__ int   g_cnt[N_EXP];
__device__ int   g_off[N_EXP];
__device__ int   g_tok[N_EXP*MAXTOK];
__device__ int   g_te[2*T_TOKENS];
__device__ int   g_tp[2*T_TOKENS];
__device__ float g_tw[2*T_TOKENS];

// ---------------- helpers ----------------
__device__ __forceinline__ uint32_t smem_u32(const void* p) {
    uint32_t a;
    asm("{ .reg .u64 t; cvta.to.shared.u64 t, %1; cvt.u32.u64 %0, t; }" : "=r"(a) : "l"(p));
    return a;
}

__device__ __forceinline__ void ldsm_x4(uint32_t* r, uint32_t addr) {
    asm volatile("ldmatrix.sync.aligned.m8n8.x4.shared.b16 {%0,%1,%2,%3}, [%4];"
        : "=r"(r[0]), "=r"(r[1]), "=r"(r[2]), "=r"(r[3]) : "r"(addr));
}

__device__ __forceinline__ void mma_bf16(float* c, const uint32_t* a, const uint32_t* b) {
    asm volatile(
        "mma.sync.aligned.m16n8k16.row.col.f32.bf16.bf16.f32 "
        "{%0,%1,%2,%3}, {%4,%5,%6,%7}, {%8,%9}, {%0,%1,%2,%3};"
        : "+f"(c[0]), "+f"(c[1]), "+f"(c[2]), "+f"(c[3])
        : "r"(a[0]), "r"(a[1]), "r"(a[2]), "r"(a[3]), "r"(b[0]), "r"(b[1]));
}

__device__ __forceinline__ void split_bf16(float x, __nv_bfloat16& h, __nv_bfloat16& l) {
    h = __float2bfloat16(x);
    l = __float2bfloat16(x - __bfloat162float(h));
}
__device__ __forceinline__ uint32_t pack2(__nv_bfloat16 a, __nv_bfloat16 b) {
    __nv_bfloat162 v = __halves2bfloat162(a, b);
    return *reinterpret_cast<uint32_t*>(&v);
}

// ---------------------------------------------------------------------------
__global__ void reset_kernel() {
    if (threadIdx.x < N_EXP) g_cnt[threadIdx.x] = 0;
}

// ---------------------------------------------------------------------------
__global__ __launch_bounds__(256) void router_kernel(
    const float* __restrict__ hs,
    const float* __restrict__ rmsw,
    const float* __restrict__ rw,
    float* __restrict__ out_logits)
{
    const int t   = blockIdx.x;
    const int tid = threadIdx.x;
    const float* x = hs + (size_t)t * H_DIM;

    float ss = 0.f;
    for (int i = tid; i < H_DIM; i += 256) { float v = x[i]; ss += v * v; }
    __shared__ float red[256];
    red[tid] = ss; __syncthreads();
    for (int s = 128; s > 0; s >>= 1) {
        if (tid < s) red[tid] += red[tid + s];
        __syncthreads();
    }
    __shared__ float s_scale;
    if (tid == 0) s_scale = rsqrtf(red[0] / (float)H_DIM + 1e-6f);
    __syncthreads();
    const float scale = s_scale;

    float acc[N_EXP];
#pragma unroll
    for (int e = 0; e < N_EXP; e++) acc[e] = 0.f;
    for (int i = tid; i < H_DIM; i += 256) {
        float v = x[i] * scale * rmsw[i];
        __nv_bfloat16 h, l; split_bf16(v, h, l);
        g_xn_hi[(size_t)t * H_DIM + i] = h;
        g_xn_lo[(size_t)t * H_DIM + i] = l;
#pragma unroll
        for (int e = 0; e < N_EXP; e++) acc[e] += v * rw[e * H_DIM + i];
    }

    __shared__ float slog[N_EXP];
    for (int e = 0; e < N_EXP; e++) {
        __syncthreads();
        red[tid] = acc[e]; __syncthreads();
        for (int s = 128; s > 0; s >>= 1) {
            if (tid < s) red[tid] += red[tid + s];
            __syncthreads();
        }
        if (tid == 0) slog[e] = red[0];
    }
    __syncthreads();

    if (tid == 0) {
        float l[N_EXP], m = -1e30f;
#pragma unroll
        for (int e = 0; e < N_EXP; e++) {
            l[e] = slog[e];
            out_logits[(size_t)t * N_EXP + e] = l[e];
            m = fmaxf(m, l[e]);
        }
        float p[N_EXP], s = 0.f;
#pragma unroll
        for (int e = 0; e < N_EXP; e++) { p[e] = expf(l[e] - m); s += p[e]; }
#pragma unroll
        for (int e = 0; e < N_EXP; e++) p[e] /= s;

        int a = 0;
#pragma unroll
        for (int e = 1; e < N_EXP; e++) if (p[e] > p[a]) a = e;
        int b = (a == 0) ? 1 : 0;
#pragma unroll
        for (int e = 0; e < N_EXP; e++) if (e != a && p[e] > p[b]) b = e;

        float wsum = p[a] + p[b] + 1e-20f;
        float wa = p[a] / wsum, wb = p[b] / wsum;

        int pa = atomicAdd(&g_cnt[a], 1);
        g_tok[a * MAXTOK + pa] = t;
        g_te[2*t] = a; g_tp[2*t] = pa; g_tw[2*t] = wa;
        int pb = atomicAdd(&g_cnt[b], 1);
        g_tok[b * MAXTOK + pb] = t;
        g_te[2*t+1] = b; g_tp[2*t+1] = pb; g_tw[2*t+1] = wb;
    }
}

// ---------------------------------------------------------------------------
__global__ void offsets_kernel() {
    int run = 0;
    for (int e = 0; e < N_EXP; e++) { g_off[e] = run; run += g_cnt[e]; }
}

// ---------------------------------------------------------------------------
// Tiled bf16x3 HMMA GEMMs. Block tile 128(M) x 64(N), K-tile 64.
// smem rows padded to 72 bf16 (144B): conflict-free ldmatrix, 16B aligned.
#define AS 72
// gemm1 smem (bf16 elements): A_hi A_lo (128x72 each), Bg/Bu hi/lo (64x72 each)
#define G1_SMEM ((2*128*AS + 4*64*AS) * 2)   // 73728 B
#define G2_SMEM ((2*128*AS + 2*64*AS) * 2)   // 55296 B

__global__ __launch_bounds__(256) void gemm1_kernel(
    const float* __restrict__ wg, const float* __restrict__ wu)
{
    const int e  = blockIdx.z;
    const int mt = blockIdx.y;
    const int nt = blockIdx.x;
    const int cnt = g_cnt[e];
    if (mt * 128 >= cnt) return;
    const int tid = threadIdx.x;
    const int wid = tid >> 5;
    const int lane = tid & 31;

    extern __shared__ __nv_bfloat16 sm[];
    __shared__ int stok[128];
    __nv_bfloat16* Ah  = sm;
    __nv_bfloat16* Al  = sm + 128*AS;
    __nv_bfloat16* Bgh = sm + 2*128*AS;
    __nv_bfloat16* Bgl = Bgh + 64*AS;
    __nv_bfloat16* Buh = Bgl + 64*AS;
    __nv_bfloat16* Bul = Buh + 64*AS;

    if (tid < 128) {
        int row = mt * 128 + tid;
        stok[tid] = (row < cnt) ? g_tok[e * MAXTOK + row] : -1;
    }

    const float* wge = wg + (size_t)e * I_DIM * H_DIM + (size_t)(nt * 64) * H_DIM;
    const float* wue = wu + (size_t)e * I_DIM * H_DIM + (size_t)(nt * 64) * H_DIM;

    float cg[2][4][4], cu[2][4][4];
#pragma unroll
    for (int i = 0; i < 2; i++)
#pragma unroll
        for (int j = 0; j < 4; j++)
#pragma unroll
            for (int k = 0; k < 4; k++) { cg[i][j][k] = 0.f; cu[i][j][k] = 0.f; }

    const int wm = wid >> 1;          // 0..3
    const int wn = wid & 1;           // 0..1
    const int lr = lane & 15;         // ldmatrix row
    const int lc = (lane >> 4) * 8;   // ldmatrix k half

    for (int kk = 0; kk < H_DIM; kk += 64) {
        __syncthreads();
        // A: 128 rows x 64 bf16 (hi & lo), gathered by token
#pragma unroll
        for (int p = 0; p < 4; p++) {
            int q = tid + p * 256;
            int r = q >> 3, c8 = (q & 7) * 8;
            int tok = stok[r];
            uint4 vh = make_uint4(0,0,0,0), vl = make_uint4(0,0,0,0);
            if (tok >= 0) {
                size_t gi = (size_t)tok * H_DIM + kk + c8;
                vh = *(const uint4*)(g_xn_hi + gi);
                vl = *(const uint4*)(g_xn_lo + gi);
            }
            int so = r * AS + c8;
            *(uint4*)(Ah + so) = vh;
            *(uint4*)(Al + so) = vl;
        }
        // B: 64 rows x 64 fp32 -> split bf16, for gate and up
#pragma unroll
        for (int p = 0; p < 4; p++) {
            int q = tid + p * 256;
            int n = q >> 4, c4 = (q & 15) * 4;
            size_t gi = (size_t)n * H_DIM + kk + c4;
            int so = n * AS + c4;
            {
                float4 v = *(const float4*)(wge + gi);
                __nv_bfloat16 h0,l0,h1,l1,h2,l2,h3,l3;
                split_bf16(v.x,h0,l0); split_bf16(v.y,h1,l1);
                split_bf16(v.z,h2,l2); split_bf16(v.w,h3,l3);
                *(uint2*)(Bgh + so) = make_uint2(pack2(h0,h1), pack2(h2,h3));
                *(uint2*)(Bgl + so) = make_uint2(pack2(l0,l1), pack2(l2,l3));
            }
            {
                float4 v = *(const float4*)(wue + gi);
                __nv_bfloat16 h0,l0,h1,l1,h2,l2,h3,l3;
                split_bf16(v.x,h0,l0); split_bf16(v.y,h1,l1);
                split_bf16(v.z,h2,l2); split_bf16(v.w,h3,l3);
                *(uint2*)(Buh + so) = make_uint2(pack2(h0,h1), pack2(h2,h3));
                *(uint2*)(Bul + so) = make_uint2(pack2(l0,l1), pack2(l2,l3));
            }
        }
        __syncthreads();

#pragma unroll
        for (int ks = 0; ks < 4; ks++) {
            uint32_t ah[2][4], al[2][4];
#pragma unroll
            for (int mf = 0; mf < 2; mf++) {
                int so = (wm*32 + mf*16 + lr) * AS + ks*16 + lc;
                ldsm_x4(ah[mf], smem_u32(Ah + so));
                ldsm_x4(al[mf], smem_u32(Al + so));
            }
            uint32_t bgh[2][4], bgl[2][4], buh[2][4], bul[2][4];
#pragma unroll
            for (int n2 = 0; n2 < 2; n2++) {
                int so = (wn*32 + n2*16 + lr) * AS + ks*16 + lc;
                ldsm_x4(bgh[n2], smem_u32(Bgh + so));
                ldsm_x4(bgl[n2], smem_u32(Bgl + so));
                ldsm_x4(buh[n2], smem_u32(Buh + so));
                ldsm_x4(bul[n2], smem_u32(Bul + so));
            }
#pragma unroll
            for (int mf = 0; mf < 2; mf++)
#pragma unroll
            for (int nf = 0; nf < 4; nf++) {
                int n2 = nf >> 1, nh = nf & 1;
                uint32_t bG [2] = { bgh[n2][nh], bgh[n2][nh+2] };
                uint32_t bGl[2] = { bgl[n2][nh], bgl[n2][nh+2] };
                mma_bf16(cg[mf][nf], ah[mf], bG);
                mma_bf16(cg[mf][nf], al[mf], bG);
                mma_bf16(cg[mf][nf], ah[mf], bGl);
                uint32_t bU [2] = { buh[n2][nh], buh[n2][nh+2] };
                uint32_t bUl[2] = { bul[n2][nh], bul[n2][nh+2] };
                mma_bf16(cu[mf][nf], ah[mf], bU);
                mma_bf16(cu[mf][nf], al[mf], bU);
                mma_bf16(cu[mf][nf], ah[mf], bUl);
            }
        }
    }

    // epilogue: h = silu(g) * u, split-bf16 packed stores
    const int off = g_off[e];
#pragma unroll
    for (int mf = 0; mf < 2; mf++)
#pragma unroll
    for (int nf = 0; nf < 4; nf++) {
        int col = nt*64 + wn*32 + nf*8 + (lane & 3)*2;
#pragma unroll
        for (int half = 0; half < 2; half++) {
            int row = mt*128 + wm*32 + mf*16 + (lane >> 2) + half*8;
            if (row < cnt) {
                float g0 = cg[mf][nf][half*2],   g1 = cg[mf][nf][half*2+1];
                float u0 = cu[mf][nf][half*2],   u1 = cu[mf][nf][half*2+1];
                float h0 = (g0 / (1.f + expf(-g0))) * u0;
                float h1 = (g1 / (1.f + expf(-g1))) * u1;
                __nv_bfloat16 a0,b0,a1,b1;
                split_bf16(h0, a0, b0); split_bf16(h1, a1, b1);
                size_t base = (size_t)(off + row) * I_DIM + col;
                *(uint32_t*)(g_h_hi + base) = pack2(a0, a1);
                *(uint32_t*)(g_h_lo + base) = pack2(b0, b1);
            }
        }
    }
}

// ---------------------------------------------------------------------------
__global__ __launch_bounds__(256) void gemm2_kernel(const float* __restrict__ wd)
{
    const int e  = blockIdx.z;
    const int mt = blockIdx.y;
    const int nt = blockIdx.x;
    const int cnt = g_cnt[e];
    if (mt * 128 >= cnt) return;
    const int tid = threadIdx.x;
    const int wid = tid >> 5;
    const int lane = tid & 31;
    const int off = g_off[e];

    extern __shared__ __nv_bfloat16 sm[];
    __nv_bfloat16* Ah = sm;
    __nv_bfloat16* Al = sm + 128*AS;
    __nv_bfloat16* Bh = sm + 2*128*AS;
    __nv_bfloat16* Bl = Bh + 64*AS;

    const float* wde = wd + (size_t)e * H_DIM * I_DIM + (size_t)(nt * 64) * I_DIM;

    float cc[2][4][4];
#pragma unroll
    for (int i = 0; i < 2; i++)
#pragma unroll
        for (int j = 0; j < 4; j++)
#pragma unroll
            for (int k = 0; k < 4; k++) cc[i][j][k] = 0.f;

    const int wm = wid >> 1;
    const int wn = wid & 1;
    const int lr = lane & 15;
    const int lc = (lane >> 4) * 8;

    for (int kk = 0; kk < I_DIM; kk += 64) {
        __syncthreads();
#pragma unroll
        for (int p = 0; p < 4; p++) {
            int q = tid + p * 256;
            int r = q >> 3, c8 = (q & 7) * 8;
            size_t gi = (size_t)(off + mt*128 + r) * I_DIM + kk + c8;
            uint4 vh = *(const uint4*)(g_h_hi + gi);
            uint4 vl = *(const uint4*)(g_h_lo + gi);
            int so = r * AS + c8;
            *(uint4*)(Ah + so) = vh;
            *(uint4*)(Al + so) = vl;
        }
#pragma unroll
        for (int p = 0; p < 4; p++) {
            int q = tid + p * 256;
            int n = q >> 4, c4 = (q & 15) * 4;
            float4 v = *(const float4*)(wde + (size_t)n * I_DIM + kk + c4);
            __nv_bfloat16 h0,l0,h1,l1,h2,l2,h3,l3;
            split_bf16(v.x,h0,l0); split_bf16(v.y,h1,l1);
            split_bf16(v.z,h2,l2); split_bf16(v.w,h3,l3);
            int so = n * AS + c4;
            *(uint2*)(Bh + so) = make_uint2(pack2(h0,h1), pack2(h2,h3));
            *(uint2*)(Bl + so) = make_uint2(pack2(l0,l1), pack2(l2,l3));
        }
        __syncthreads();

#pragma unroll
        for (int ks = 0; ks < 4; ks++) {
            uint32_t ah[2][4], al[2][4];
#pragma unroll
            for (int mf = 0; mf < 2; mf++) {
                int so = (wm*32 + mf*16 + lr) * AS + ks*16 + lc;
                ldsm_x4(ah[mf], smem_u32(Ah + so));
                ldsm_x4(al[mf], smem_u32(Al + so));
            }
            uint32_t bh[2][4], bl[2][4];
#pragma unroll
            for (int n2 = 0; n2 < 2; n2++) {
                int so = (wn*32 + n2*16 + lr) * AS + ks*16 + lc;
                ldsm_x4(bh[n2], smem_u32(Bh + so));
                ldsm_x4(bl[n2], smem_u32(Bl + so));
            }
#pragma unroll
            for (int mf = 0; mf < 2; mf++)
#pragma unroll
            for (int nf = 0; nf < 4; nf++) {
                int n2 = nf >> 1, nh = nf & 1;
                uint32_t bH[2] = { bh[n2][nh], bh[n2][nh+2] };
                uint32_t bL[2] = { bl[n2][nh], bl[n2][nh+2] };
                mma_bf16(cc[mf][nf], ah[mf], bH);
                mma_bf16(cc[mf][nf], al[mf], bH);
                mma_bf16(cc[mf][nf], ah[mf], bL);
            }
        }
    }

    // epilogue: store unscaled y rows (fp32)
#pragma unroll
    for (int mf = 0; mf < 2; mf++)
#pragma unroll
    for (int nf = 0; nf < 4; nf++) {
        int col = nt*64 + wn*32 + nf*8 + (lane & 3)*2;
#pragma unroll
        for (int half = 0; half < 2; half++) {
            int row = mt*128 + wm*32 + mf*16 + (lane >> 2) + half*8;
            if (row < cnt) {
                float2 v = make_float2(cc[mf][nf][half*2], cc[mf][nf][half*2+1]);
                *(float2*)(g_y + (size_t)(off + row) * H_DIM + col) = v;
            }
        }
    }
}

// ---------------------------------------------------------------------------
__global__ __launch_bounds__(256) void combine_kernel(float* __restrict__ out)
{
    const int t = blockIdx.x;
    const int tid = threadIdx.x;
    const int e0 = g_te[2*t],   p0 = g_tp[2*t];
    const int e1 = g_te[2*t+1], p1 = g_tp[2*t+1];
    const float w0 = g_tw[2*t], w1 = g_tw[2*t+1];
    const float* y0 = g_y + (size_t)(g_off[e0] + p0) * H_DIM;
    const float* y1 = g_y + (size_t)(g_off[e1] + p1) * H_DIM;
    float* o = out + (size_t)t * H_DIM;
#pragma unroll
    for (int it = 0; it < 2; it++) {
        int i = (tid + it * 256) * 4;
        float4 a = *(const float4*)(y0 + i);
        float4 b = *(const float4*)(y1 + i);
        float4 r;
        r.x = w0 * a.x + w1 * b.x;
        r.y = w0 * a.y + w1 * b.y;
        r.z = w0 * a.z + w1 * b.z;
        r.w = w0 * a.w + w1 * b.w;
        *(float4*)(o + i) = r;
    }
}

// ---------------------------------------------------------------------------
extern "C" void kernel_launch(void* const* d_in, const int* in_sizes, int n_in,
                              void* d_out, int out_size)
{
    const float* hs   = (const float*)d_in[0];
    const float* rmsw = (const float*)d_in[1];
    const float* rw   = (const float*)d_in[2];
    const float* wg   = (const float*)d_in[3];
    const float* wu   = (const float*)d_in[4];
    const float* wd   = (const float*)d_in[5];

    float* out        = (float*)d_out;
    float* out_logits = (float*)d_out + (size_t)T_TOKENS * H_DIM;

    cudaFuncSetAttribute(gemm1_kernel, cudaFuncAttributeMaxDynamicSharedMemorySize, G1_SMEM);
    cudaFuncSetAttribute(gemm2_kernel, cudaFuncAttributeMaxDynamicSharedMemorySize, G2_SMEM);

    reset_kernel<<<1, 32>>>();
    router_kernel<<<T_TOKENS, 256>>>(hs, rmsw, rw, out_logits);
    offsets_kernel<<<1, 1>>>();

    dim3 g1(I_DIM / 64, T_TOKENS / 128, N_EXP);   // 22 x 64 x 8
    gemm1_kernel<<<g1, 256, G1_SMEM>>>(wg, wu);

    dim3 g2(H_DIM / 64, T_TOKENS / 128, N_EXP);   // 32 x 64 x 8
    gemm2_kernel<<<g2, 256, G2_SMEM>>>(wd);

    combine_kernel<<<T_TOKENS, 256>>>(out);
}